// round 5
// baseline (speedup 1.0000x reference)
#include <cuda_runtime.h>

#define HH   112
#define WWD  112
#define HW   12544
#define CIN  128
#define CO   64
#define BATCH 2

// parity-space constants: K=7, D=1, L=56
#define PL   56
#define PT   8          // parity tile = 8x8
#define HALO 14         // 8 + 6
#define PAD  68         // floats per loc -> 17 float4 slots (odd) => conflict-free
#define HALO_MAX (HALO * HALO)   // 196

// GEMM W smem: [m][kk][o] with row stride 68 floats (16B-aligned, odd /4)
#define WST  68
#define WCH  (32 * WST)   // 2176 floats per matrix per chunk

typedef unsigned long long ull;

// scratch
__device__ __align__(128) float g_q[BATCH * HW * CO];
__device__ __align__(128) float g_k[BATCH * HW * CO];
__device__ __align__(128) float g_v[BATCH * HW * CO];

// ---------------------------------------------------------------------------
__device__ __forceinline__ ull pk2(float x, float y) {
    ull r; asm("mov.b64 %0, {%1,%2};" : "=l"(r) : "f"(x), "f"(y)); return r;
}
__device__ __forceinline__ void upk2(ull v, float& x, float& y) {
    asm("mov.b64 {%0,%1}, %2;" : "=f"(x), "=f"(y) : "l"(v));
}
__device__ __forceinline__ void fma2(ull& d, ull a, ull b) {
    asm("fma.rn.f32x2 %0, %1, %2, %3;" : "=l"(d) : "l"(a), "l"(b), "l"(d));
}

// ---------------------------------------------------------------------------
// Fused QKV GEMM: tile 128 px x 64 out x 3 mats, 512 threads (R3 structure).
// Thread: 4 px x 4 out (as 2 f32x2 out-pairs) x 3 mats = 24 ull accumulators.
// W transposed on the fly during the smem load (no separate transpose kernel).
// ---------------------------------------------------------------------------
__global__ __launch_bounds__(512) void qkv_gemm(
    const float* __restrict__ x,
    const float* __restrict__ Wq, const float* __restrict__ Wk,
    const float* __restrict__ Wv,
    const float* __restrict__ bq, const float* __restrict__ bk,
    const float* __restrict__ bv)
{
    __shared__ float Xs[32 * 128];          // [c][px] 16KB
    __shared__ float Ws[3 * WCH];           // [m][c][o] stride 68, ~25.5KB

    const int b   = blockIdx.y;
    const int hw0 = blockIdx.x * 128;
    const int tid = threadIdx.x;
    const int tp  = tid >> 4;               // 0..31 (4 px each)
    const int to  = tid & 15;               // 0..15 (4 out each)

    ull acc[3][4][2];
#pragma unroll
    for (int m = 0; m < 3; m++)
#pragma unroll
        for (int i = 0; i < 4; i++)
#pragma unroll
            for (int j = 0; j < 2; j++) acc[m][i][j] = 0ull;

    const float* xb = x + (size_t)b * CIN * HW + hw0;
    const float* Wmats[3] = { Wq, Wk, Wv };

    const int wc  = tid >> 4;               // 0..31 channel for W load
    const int wo4 = tid & 15;               // 0..15 out-quad for W load

    for (int kc = 0; kc < CIN; kc += 32) {
        __syncthreads();
        // Xs: 32 c x 128 px = 1024 float4, 2 per thread, coalesced
#pragma unroll
        for (int t = 0; t < 2; t++) {
            int idx = tid + t * 512;
            int c   = idx >> 5;
            int p4  = idx & 31;
            ((float4*)Xs)[c * 32 + p4] =
                *(const float4*)(xb + (size_t)(kc + c) * HW + p4 * 4);
        }
        // Ws: transpose-on-load. Thread gathers 4 outputs of one channel
        // (4 row-strided LDG.32), stores one conflict-free STS.128.
#pragma unroll
        for (int m = 0; m < 3; m++) {
            const float* wp = Wmats[m] + (size_t)(wo4 * 4) * CIN + kc + wc;
            float4 wv = make_float4(wp[0], wp[CIN], wp[2 * CIN], wp[3 * CIN]);
            *(float4*)(Ws + m * WCH + wc * WST + wo4 * 4) = wv;
        }
        __syncthreads();

#pragma unroll 4
        for (int kk = 0; kk < 32; kk++) {
            float4 af = *(const float4*)(Xs + kk * 128 + tp * 4);
            ull a0 = pk2(af.x, af.x), a1 = pk2(af.y, af.y);
            ull a2_ = pk2(af.z, af.z), a3 = pk2(af.w, af.w);
#pragma unroll
            for (int m = 0; m < 3; m++) {
                ulonglong2 w2 = *(const ulonglong2*)(Ws + m * WCH + kk * WST + to * 4);
                fma2(acc[m][0][0], a0, w2.x);  fma2(acc[m][0][1], a0, w2.y);
                fma2(acc[m][1][0], a1, w2.x);  fma2(acc[m][1][1], a1, w2.y);
                fma2(acc[m][2][0], a2_, w2.x); fma2(acc[m][2][1], a2_, w2.y);
                fma2(acc[m][3][0], a3, w2.x);  fma2(acc[m][3][1], a3, w2.y);
            }
        }
    }

    // epilogue: + bias, * scale, store (b, hw, o) with o contiguous
    const float* biases[3] = { bq, bk, bv };
    float* outs[3] = { g_q, g_k, g_v };
    const float scales[3] = { 0.125f, 1.0f, 1.0f };
#pragma unroll
    for (int m = 0; m < 3; m++) {
        float4 bs = *(const float4*)(biases[m] + to * 4);
        float s = scales[m];
        float* ob = outs[m] + ((size_t)b * HW + hw0 + tp * 4) * CO + to * 4;
#pragma unroll
        for (int i = 0; i < 4; i++) {
            float r0, r1, r2, r3;
            upk2(acc[m][i][0], r0, r1);
            upk2(acc[m][i][1], r2, r3);
            float4 v = make_float4((r0 + bs.x) * s, (r1 + bs.y) * s,
                                   (r2 + bs.z) * s, (r3 + bs.w) * s);
            *(float4*)(ob + (size_t)i * CO) = v;
        }
    }
}

// ---------------------------------------------------------------------------
// Fused neighborhood attention, parity-tiled (exact R3 version, 92.2us run).
// ---------------------------------------------------------------------------
__global__ __launch_bounds__(256, 2) void natt_kernel(float* __restrict__ outp)
{
    extern __shared__ float sm[];
    float* Ks = sm;
    float* Vs = sm + HALO_MAX * PAD;

    const int z    = blockIdx.z;
    const int b    = z >> 2;
    const int parh = (z >> 1) & 1;
    const int parw = z & 1;
    const int ph0  = blockIdx.y * PT;
    const int pw0  = blockIdx.x * PT;
    const int r0p  = max(0, ph0 - 3);
    const int c0p  = max(0, pw0 - 3);
    const int rows = min(HALO, PL - r0p);
    const int cols = min(HALO, PL - c0p);
    const int tid  = threadIdx.x;

    // halo load: 16 threads per loc, float4 each
    {
        const float* kb = g_k + (size_t)b * HW * CO;
        const float* vb = g_v + (size_t)b * HW * CO;
        const int l16 = tid & 15;
        const int nloc = rows * cols;
        for (int loc = tid >> 4; loc < nloc; loc += 16) {
            int lr = loc / cols;
            int lc = loc - lr * cols;
            int h  = 2 * (r0p + lr) + parh;
            int w  = 2 * (c0p + lc) + parw;
            size_t g = ((size_t)h * WWD + w) * CO + l16 * 4;
            int s = loc * PAD + l16 * 4;
            *(float4*)(Ks + s) = *(const float4*)(kb + g);
            *(float4*)(Vs + s) = *(const float4*)(vb + g);
        }
    }
    __syncthreads();

    const int p   = tid >> 2;     // parity pixel 0..63
    const int sub = tid & 3;
    const int ph  = ph0 + (p >> 3);
    const int pw  = pw0 + (p & 7);
    const int h   = 2 * ph + parh;
    const int w   = 2 * pw + parw;

    const float* qp = g_q + ((size_t)b * HW + (size_t)h * WWD + w) * CO + sub * 16;
    ulonglong2 qa = *(const ulonglong2*)(qp);
    ulonglong2 qb_ = *(const ulonglong2*)(qp + 4);
    ulonglong2 qc = *(const ulonglong2*)(qp + 8);
    ulonglong2 qd = *(const ulonglong2*)(qp + 12);
    ull qq[8] = { qa.x, qa.y, qb_.x, qb_.y, qc.x, qc.y, qd.x, qd.y };

    const int wsh = min(max(ph - 3, 0), PL - 7);
    const int wsw = min(max(pw - 3, 0), PL - 7);
    const int rowstride = cols * PAD;
    int rb[7], cb[7];
#pragma unroll
    for (int j = 0; j < 7; j++) {
        rb[j] = (wsh + j - r0p) * rowstride + sub * 16;
        cb[j] = (wsw + j - c0p) * PAD;
    }

    float sc[49];
#pragma unroll
    for (int jh = 0; jh < 7; jh++) {
#pragma unroll
        for (int jw = 0; jw < 7; jw++) {
            const float* kp = Ks + rb[jh] + cb[jw];
            ull s2 = 0ull;
#pragma unroll
            for (int i = 0; i < 4; i++) {
                ulonglong2 kv = *(const ulonglong2*)(kp + i * 4);
                fma2(s2, qq[2 * i],     kv.x);
                fma2(s2, qq[2 * i + 1], kv.y);
            }
            float sx, sy;
            upk2(s2, sx, sy);
            float s = sx + sy;
            s += __shfl_xor_sync(0xffffffffu, s, 1);
            s += __shfl_xor_sync(0xffffffffu, s, 2);
            sc[jh * 7 + jw] = s;
        }
    }

    float m = sc[0];
#pragma unroll
    for (int j = 1; j < 49; j++) m = fmaxf(m, sc[j]);
    float sum = 0.f;
#pragma unroll
    for (int j = 0; j < 49; j++) { sc[j] = __expf(sc[j] - m); sum += sc[j]; }
    const float inv = 1.0f / sum;

    ull a2[8];
#pragma unroll
    for (int i = 0; i < 8; i++) a2[i] = 0ull;
#pragma unroll
    for (int jh = 0; jh < 7; jh++) {
#pragma unroll
        for (int jw = 0; jw < 7; jw++) {
            float pj = sc[jh * 7 + jw] * inv;
            ull pp = pk2(pj, pj);
            const float* vp = Vs + rb[jh] + cb[jw];
#pragma unroll
            for (int i = 0; i < 4; i++) {
                ulonglong2 vv = *(const ulonglong2*)(vp + i * 4);
                fma2(a2[2 * i],     pp, vv.x);
                fma2(a2[2 * i + 1], pp, vv.y);
            }
        }
    }

    float* ob = outp + ((size_t)b * CO + sub * 16) * HW + (size_t)h * WWD + w;
#pragma unroll
    for (int i = 0; i < 8; i++) {
        float x0, x1;
        upk2(a2[i], x0, x1);
        ob[(size_t)(2 * i) * HW]     = x0;
        ob[(size_t)(2 * i + 1) * HW] = x1;
    }
}

// ---------------------------------------------------------------------------
extern "C" void kernel_launch(void* const* d_in, const int* in_sizes, int n_in,
                              void* d_out, int out_size)
{
    (void)in_sizes; (void)n_in; (void)out_size;
    const float* x  = (const float*)d_in[0];
    const float* Wq = (const float*)d_in[1];
    const float* bq = (const float*)d_in[2];
    const float* Wk = (const float*)d_in[3];
    const float* bk = (const float*)d_in[4];
    const float* Wv = (const float*)d_in[5];
    const float* bv = (const float*)d_in[6];
    float* out = (float*)d_out;

    qkv_gemm<<<dim3(98, 2), 512>>>(x, Wq, Wk, Wv, bq, bk, bv);  // 98*128 = 12544 px

    const int smem = 2 * HALO_MAX * PAD * (int)sizeof(float);   // 106624
    cudaFuncSetAttribute(natt_kernel, cudaFuncAttributeMaxDynamicSharedMemorySize, smem);
    natt_kernel<<<dim3(7, 7, 8), 256, smem>>>(out);
}

// round 6
// speedup vs baseline: 2.1468x; 2.1468x over previous
#include <cuda_runtime.h>

#define HH   112
#define WWD  112
#define HW   12544
#define CIN  128
#define CO   64
#define BATCH 2

// parity-space constants: K=7, D=1, L=56
#define PL   56
#define PT   8          // parity tile = 8x8
#define HALO 14         // 8 + 6
#define PAD  68         // floats per loc -> 17 float4 slots
#define HALO_MAX (HALO * HALO)   // 196

typedef unsigned long long ull;

// scratch
__device__ __align__(128) float g_q[BATCH * HW * CO];
__device__ __align__(128) float g_k[BATCH * HW * CO];
__device__ __align__(128) float g_v[BATCH * HW * CO];
__device__ __align__(128) float g_Wt[3 * CIN * CO];   // [m][c][o]

// ---------------------------------------------------------------------------
__device__ __forceinline__ ull pk2(float x, float y) {
    ull r; asm("mov.b64 %0, {%1,%2};" : "=l"(r) : "f"(x), "f"(y)); return r;
}
__device__ __forceinline__ void upk2(ull v, float& x, float& y) {
    asm("mov.b64 {%0,%1}, %2;" : "=f"(x), "=f"(y) : "l"(v));
}
__device__ __forceinline__ void fma2(ull& d, ull a, ull b) {
    asm("fma.rn.f32x2 %0, %1, %2, %3;" : "=l"(d) : "l"(a), "l"(b), "l"(d));
}

// ---------------------------------------------------------------------------
// One-shot W transpose: g_Wt[m][c][o] = Wm[o][c]. (measured 4.5us, keep)
// ---------------------------------------------------------------------------
__global__ void transposeW(const float* __restrict__ Wq,
                           const float* __restrict__ Wk,
                           const float* __restrict__ Wv)
{
    int idx = blockIdx.x * 256 + threadIdx.x;      // 0..24575
    int m   = idx >> 13;
    int rem = idx & 8191;
    int o   = rem >> 7;
    int c   = rem & 127;
    const float* W = (m == 0) ? Wq : (m == 1) ? Wk : Wv;
    g_Wt[m * 8192 + c * 64 + o] = W[o * 128 + c];
}

// ---------------------------------------------------------------------------
// Fused QKV GEMM: tile 128 px x 64 out x 3 mats, 512 threads.
// R3 load scheme (coalesced float4 from g_Wt / x), out-pair f32x2 compute:
// per kk: 1 X-LDS + 3 W-LDS (consumed directly as f32x2 pairs) + 4 movs + 24 FFMA2.
// ---------------------------------------------------------------------------
__global__ __launch_bounds__(512) void qkv_gemm(
    const float* __restrict__ x,
    const float* __restrict__ bq, const float* __restrict__ bk,
    const float* __restrict__ bv)
{
    __shared__ float Xs[32 * 128];        // [c][px] 16KB
    __shared__ float Ws[3 * 32 * 64];     // [m][c][o] 24KB

    const int b   = blockIdx.y;
    const int hw0 = blockIdx.x * 128;
    const int tid = threadIdx.x;
    const int tp  = tid >> 4;             // 0..31 (4 px each)
    const int to  = tid & 15;             // 0..15 (4 out each)

    ull acc[3][4][2];
#pragma unroll
    for (int m = 0; m < 3; m++)
#pragma unroll
        for (int i = 0; i < 4; i++)
#pragma unroll
            for (int j = 0; j < 2; j++) acc[m][i][j] = 0ull;

    const float* xb = x + (size_t)b * CIN * HW + hw0;

    for (int kc = 0; kc < CIN; kc += 32) {
        __syncthreads();
        // Xs: 32 c x 128 px = 1024 float4, 2 per thread, coalesced
#pragma unroll
        for (int t = 0; t < 2; t++) {
            int idx = tid + t * 512;
            int c   = idx >> 5;
            int p4  = idx & 31;
            ((float4*)Xs)[c * 32 + p4] =
                *(const float4*)(xb + (size_t)(kc + c) * HW + p4 * 4);
        }
        // Ws: 3 x 32 c x 64 o = 1536 float4, 3 per thread, coalesced from g_Wt
#pragma unroll
        for (int t = 0; t < 3; t++) {
            int idx = tid + t * 512;      // == dest slot
            int m   = idx >> 9;
            int rem = idx & 511;
            int kk  = rem >> 4;
            int o4  = rem & 15;
            ((float4*)Ws)[idx] =
                *(const float4*)(g_Wt + m * 8192 + (kc + kk) * 64 + o4 * 4);
        }
        __syncthreads();

#pragma unroll 4
        for (int kk = 0; kk < 32; kk++) {
            float4 af = *(const float4*)(Xs + kk * 128 + tp * 4);
            ull a0 = pk2(af.x, af.x), a1 = pk2(af.y, af.y);
            ull a2_ = pk2(af.z, af.z), a3 = pk2(af.w, af.w);
#pragma unroll
            for (int m = 0; m < 3; m++) {
                ulonglong2 w2 = *(const ulonglong2*)(Ws + m * 2048 + kk * 64 + to * 4);
                fma2(acc[m][0][0], a0, w2.x);  fma2(acc[m][0][1], a0, w2.y);
                fma2(acc[m][1][0], a1, w2.x);  fma2(acc[m][1][1], a1, w2.y);
                fma2(acc[m][2][0], a2_, w2.x); fma2(acc[m][2][1], a2_, w2.y);
                fma2(acc[m][3][0], a3, w2.x);  fma2(acc[m][3][1], a3, w2.y);
            }
        }
    }

    // epilogue: + bias, * scale, store (b, hw, o) with o contiguous
    const float* biases[3] = { bq, bk, bv };
    float* outs[3] = { g_q, g_k, g_v };
    const float scales[3] = { 0.125f, 1.0f, 1.0f };
#pragma unroll
    for (int m = 0; m < 3; m++) {
        float4 bs = *(const float4*)(biases[m] + to * 4);
        float s = scales[m];
        float* ob = outs[m] + ((size_t)b * HW + hw0 + tp * 4) * CO + to * 4;
#pragma unroll
        for (int i = 0; i < 4; i++) {
            float r0, r1, r2, r3;
            upk2(acc[m][i][0], r0, r1);
            upk2(acc[m][i][1], r2, r3);
            float4 v = make_float4((r0 + bs.x) * s, (r1 + bs.y) * s,
                                   (r2 + bs.z) * s, (r3 + bs.w) * s);
            *(float4*)(ob + (size_t)i * CO) = v;
        }
    }
}

// ---------------------------------------------------------------------------
// Fused neighborhood attention, parity-tiled.
// LANE REMAP: warp = tile row; sub = lane>>3, pixel-col = lane&7.
// Each 8-lane LDS phase: constant sub, pw=0..7 -> slots stride 17 mod 8
// covers all bank groups => conflict-free (borders degrade to broadcast).
// ---------------------------------------------------------------------------
__global__ __launch_bounds__(256, 2) void natt_kernel(float* __restrict__ outp)
{
    extern __shared__ float sm[];
    float* Ks = sm;
    float* Vs = sm + HALO_MAX * PAD;

    const int z    = blockIdx.z;
    const int b    = z >> 2;
    const int parh = (z >> 1) & 1;
    const int parw = z & 1;
    const int ph0  = blockIdx.y * PT;
    const int pw0  = blockIdx.x * PT;
    const int r0p  = max(0, ph0 - 3);
    const int c0p  = max(0, pw0 - 3);
    const int rows = min(HALO, PL - r0p);
    const int cols = min(HALO, PL - c0p);
    const int tid  = threadIdx.x;

    // halo load: 16 threads per loc, float4 each
    {
        const float* kb = g_k + (size_t)b * HW * CO;
        const float* vb = g_v + (size_t)b * HW * CO;
        const int l16 = tid & 15;
        const int nloc = rows * cols;
        for (int loc = tid >> 4; loc < nloc; loc += 16) {
            int lr = loc / cols;
            int lc = loc - lr * cols;
            int h  = 2 * (r0p + lr) + parh;
            int w  = 2 * (c0p + lc) + parw;
            size_t g = ((size_t)h * WWD + w) * CO + l16 * 4;
            int s = loc * PAD + l16 * 4;
            *(float4*)(Ks + s) = *(const float4*)(kb + g);
            *(float4*)(Vs + s) = *(const float4*)(vb + g);
        }
    }
    __syncthreads();

    const int lane = tid & 31;
    const int warp = tid >> 5;        // tile row 0..7
    const int sub  = lane >> 3;       // channel quarter 0..3
    const int pwl  = lane & 7;        // tile col 0..7
    const int ph   = ph0 + warp;
    const int pw   = pw0 + pwl;
    const int h    = 2 * ph + parh;
    const int w    = 2 * pw + parw;

    const float* qp = g_q + ((size_t)b * HW + (size_t)h * WWD + w) * CO + sub * 16;
    ulonglong2 qa = *(const ulonglong2*)(qp);
    ulonglong2 qb_ = *(const ulonglong2*)(qp + 4);
    ulonglong2 qc = *(const ulonglong2*)(qp + 8);
    ulonglong2 qd = *(const ulonglong2*)(qp + 12);
    ull qq[8] = { qa.x, qa.y, qb_.x, qb_.y, qc.x, qc.y, qd.x, qd.y };

    const int wsh = min(max(ph - 3, 0), PL - 7);
    const int wsw = min(max(pw - 3, 0), PL - 7);
    const int rowstride = cols * PAD;
    int rb[7], cb[7];
#pragma unroll
    for (int j = 0; j < 7; j++) {
        rb[j] = (wsh + j - r0p) * rowstride + sub * 16;
        cb[j] = (wsw + j - c0p) * PAD;
    }

    float sc[49];
#pragma unroll
    for (int jh = 0; jh < 7; jh++) {
#pragma unroll
        for (int jw = 0; jw < 7; jw++) {
            const float* kp = Ks + rb[jh] + cb[jw];
            ull s2 = 0ull;
#pragma unroll
            for (int i = 0; i < 4; i++) {
                ulonglong2 kv = *(const ulonglong2*)(kp + i * 4);
                fma2(s2, qq[2 * i],     kv.x);
                fma2(s2, qq[2 * i + 1], kv.y);
            }
            float sx, sy;
            upk2(s2, sx, sy);
            float s = sx + sy;
            s += __shfl_xor_sync(0xffffffffu, s, 8);
            s += __shfl_xor_sync(0xffffffffu, s, 16);
            sc[jh * 7 + jw] = s;
        }
    }

    float m = sc[0];
#pragma unroll
    for (int j = 1; j < 49; j++) m = fmaxf(m, sc[j]);
    float sum = 0.f;
#pragma unroll
    for (int j = 0; j < 49; j++) { sc[j] = __expf(sc[j] - m); sum += sc[j]; }
    const float inv = 1.0f / sum;

    ull a2[8];
#pragma unroll
    for (int i = 0; i < 8; i++) a2[i] = 0ull;
#pragma unroll
    for (int jh = 0; jh < 7; jh++) {
#pragma unroll
        for (int jw = 0; jw < 7; jw++) {
            float pj = sc[jh * 7 + jw] * inv;
            ull pp = pk2(pj, pj);
            const float* vp = Vs + rb[jh] + cb[jw];
#pragma unroll
            for (int i = 0; i < 4; i++) {
                ulonglong2 vv = *(const ulonglong2*)(vp + i * 4);
                fma2(a2[2 * i],     pp, vv.x);
                fma2(a2[2 * i + 1], pp, vv.y);
            }
        }
    }

    float* ob = outp + ((size_t)b * CO + sub * 16) * HW + (size_t)h * WWD + w;
#pragma unroll
    for (int i = 0; i < 8; i++) {
        float x0, x1;
        upk2(a2[i], x0, x1);
        ob[(size_t)(2 * i) * HW]     = x0;
        ob[(size_t)(2 * i + 1) * HW] = x1;
    }
}

// ---------------------------------------------------------------------------
extern "C" void kernel_launch(void* const* d_in, const int* in_sizes, int n_in,
                              void* d_out, int out_size)
{
    (void)in_sizes; (void)n_in; (void)out_size;
    const float* x  = (const float*)d_in[0];
    const float* Wq = (const float*)d_in[1];
    const float* bq = (const float*)d_in[2];
    const float* Wk = (const float*)d_in[3];
    const float* bk = (const float*)d_in[4];
    const float* Wv = (const float*)d_in[5];
    const float* bv = (const float*)d_in[6];
    float* out = (float*)d_out;

    transposeW<<<96, 256>>>(Wq, Wk, Wv);
    qkv_gemm<<<dim3(98, 2), 512>>>(x, bq, bk, bv);   // 98*128 = 12544 px

    const int smem = 2 * HALO_MAX * PAD * (int)sizeof(float);   // 106624
    cudaFuncSetAttribute(natt_kernel, cudaFuncAttributeMaxDynamicSharedMemorySize, smem);
    natt_kernel<<<dim3(7, 7, 8), 256, smem>>>(out);
}